// round 5
// baseline (speedup 1.0000x reference)
#include <cuda_runtime.h>
#include <cstdint>

// Problem constants (fixed by reference): B=64, MEL_MAX=2000, TEXT_MAX=256
#define BATCH   64
#define MEL_MAX 2000
#define TXT_MAX 256
// 1/(2*g^2), g=0.2 -> 12.5
#define A_COEF  12.5f

#define NROWS   (BATCH * MEL_MAX)        // 128000
#define NBLK    888                      // 148 SMs * 6 CTAs
#define NTHR    256                      // 8 warps per CTA

// Scratch (__device__ globals — no allocation allowed)
__device__ double       g_block[NBLK];
__device__ unsigned int g_count = 0;

// ---------------------------------------------------------------------------
// Single fused kernel:
//   phase 1: persistent warp-per-row grid-stride. Lane owns 8 contiguous
//            text positions (n = 8*lane .. 8*lane+7). Gaussian via
//            multiplicative recurrence (2 MUFU per row-chunk; q2 from a
//            shared per-batch constant table).
//   phase 2: each block writes one double partial; the LAST block (atomic
//            ticket) reduces all partials + the active-area normalizer and
//            writes the final scalar. Deterministic: fixed partial set,
//            fixed summation order.
// ---------------------------------------------------------------------------
__global__ __launch_bounds__(NTHR) void fused_kernel(
    const float* __restrict__ pred,
    const int*   __restrict__ tlen,
    const int*   __restrict__ mlen,
    float*       __restrict__ out)
{
    // ---- per-batch constant table ----
    __shared__ float4 cst[BATCH];   // {inv_tl, inv_ml, q2, ml(bits)}
    __shared__ int    stl[BATCH];
    if (threadIdx.x < BATCH) {
        const int tl = __ldg(&tlen[threadIdx.x]);
        const int ml = __ldg(&mlen[threadIdx.x]);
        const float inv_tl = 1.0f / (float)tl;
        const float inv_ml = 1.0f / (float)ml;
        const float q2 = __expf(-2.0f * A_COEF * inv_tl * inv_tl);
        cst[threadIdx.x] = make_float4(inv_tl, inv_ml, q2, __int_as_float(ml));
        stl[threadIdx.x] = tl;
    }
    __syncthreads();

    const int lane   = threadIdx.x & 31;
    const int wid    = threadIdx.x >> 5;
    const int gwarp  = blockIdx.x * 8 + wid;
    const int nwarps = NBLK * 8;
    const int n0     = lane * 8;

    float tsp  = 0.0f;   // sum p
    float tsep = 0.0f;   // sum E*p

    for (int row = gwarp; row < NROWS; row += nwarps) {
        const int b = row / MEL_MAX;
        const int t = row - b * MEL_MAX;

        const float4 c = cst[b];
        const int ml = __float_as_int(c.w);
        if (t >= ml) continue;

        int count = stl[b] - n0;
        if (count <= 0) continue;
        if (count > 8) count = 8;

        const float inv_tl = c.x;
        const float beta   = (float)t * c.y;

        // E(n) = exp(-A (n*inv_tl - beta)^2); ratio recurrence:
        // m(n) = exp(inv_tl*(2A*beta - A*inv_tl*(2n+1))), m *= q2 each step
        const float d0 = (float)n0 * inv_tl - beta;
        float E = __expf(-A_COEF * d0 * d0);
        float m = __expf(inv_tl * (2.0f * A_COEF * beta
                         - A_COEF * inv_tl * (float)(2 * n0 + 1)));
        const float q2 = c.z;

        const float4* rp = (const float4*)(pred + (size_t)row * TXT_MAX + n0);
        const float4 v0 = __ldg(rp);
        const float4 v1 = __ldg(rp + 1);
        float vals[8] = {v0.x, v0.y, v0.z, v0.w, v1.x, v1.y, v1.z, v1.w};

        #pragma unroll
        for (int j = 0; j < 8; j++) {
            const float pj = (j < count) ? vals[j] : 0.0f;
            tsp  += pj;
            tsep  = fmaf(E, pj, tsep);
            E *= m;
            m *= q2;
        }
    }

    // ---- block reduction: loss contribution = sum((1-E)p) = tsp - tsep ----
    float tot = tsp - tsep;
    #pragma unroll
    for (int o = 16; o > 0; o >>= 1)
        tot += __shfl_xor_sync(0xFFFFFFFFu, tot, o);

    __shared__ double wsum[8];
    if (lane == 0) wsum[wid] = (double)tot;
    __syncthreads();

    __shared__ bool amLast;
    if (threadIdx.x == 0) {
        double s = 0.0;
        #pragma unroll
        for (int k = 0; k < 8; k++) s += wsum[k];
        g_block[blockIdx.x] = s;
        __threadfence();
        const unsigned int v = atomicAdd(&g_count, 1u);
        amLast = (v == NBLK - 1);
    }
    __syncthreads();

    // ---- last block: final reduction + normalizer + output ----
    if (amLast) {
        __threadfence();
        double s = 0.0;
        for (int k = threadIdx.x; k < NBLK; k += NTHR)
            s += __ldcg(&g_block[k]);
        double a = 0.0;
        if (threadIdx.x < BATCH)
            a = (double)__ldg(&tlen[threadIdx.x]) * (double)__ldg(&mlen[threadIdx.x]);

        #pragma unroll
        for (int o = 16; o > 0; o >>= 1) {
            s += __shfl_xor_sync(0xFFFFFFFFu, s, o);
            a += __shfl_xor_sync(0xFFFFFFFFu, a, o);
        }

        __shared__ double sv[8], sa[8];
        if (lane == 0) { sv[wid] = s; sa[wid] = a; }
        __syncthreads();

        if (threadIdx.x == 0) {
            double tv = 0.0, ta = 0.0;
            #pragma unroll
            for (int k = 0; k < 8; k++) { tv += sv[k]; ta += sa[k]; }
            out[0] = (float)(tv / ta);   // attention_weight = 1.0
            g_count = 0;                 // reset for next graph replay
        }
    }
}

// ---------------------------------------------------------------------------
// Inputs (metadata order): targets (unused), predictions, text_lengths,
// mel_lengths. Output: single float.
// ---------------------------------------------------------------------------
extern "C" void kernel_launch(void* const* d_in, const int* in_sizes, int n_in,
                              void* d_out, int out_size)
{
    (void)in_sizes; (void)n_in; (void)out_size;
    const float* pred = (const float*)d_in[1];
    const int*   tlen = (const int*)d_in[2];
    const int*   mlen = (const int*)d_in[3];
    float*       out  = (float*)d_out;

    fused_kernel<<<NBLK, NTHR>>>(pred, tlen, mlen, out);
}

// round 6
// speedup vs baseline: 1.1818x; 1.1818x over previous
#include <cuda_runtime.h>
#include <cstdint>

// Problem constants: B=64, MEL_MAX=2000, TEXT_MAX=256, g=0.2
#define BATCH   64
#define MEL_MAX 2000
#define TXT_MAX 256
#define A_COEF  12.5f            // 1/(2 g^2)

#define SSTRIDE 39               // t-interleave stride (gives near-perfect balance)
#define NBLK    (BATCH * SSTRIDE)  // 2496 blocks
#define NTHR    256

typedef unsigned long long u64;

// Scratch (__device__ globals — no allocation allowed)
__device__ double       g_block[NBLK];
__device__ unsigned int g_count = 0;

// ---- packed f32x2 helpers (Blackwell) ----
__device__ __forceinline__ u64 pk2(float lo, float hi) {
    u64 r; asm("mov.b64 %0,{%1,%2};" : "=l"(r) : "f"(lo), "f"(hi)); return r;
}
__device__ __forceinline__ void unpk2(u64 a, float& lo, float& hi) {
    asm("mov.b64 {%0,%1},%2;" : "=f"(lo), "=f"(hi) : "l"(a));
}
__device__ __forceinline__ u64 mul2(u64 a, u64 b) {
    u64 r; asm("mul.rn.f32x2 %0,%1,%2;" : "=l"(r) : "l"(a), "l"(b)); return r;
}
__device__ __forceinline__ u64 add2(u64 a, u64 b) {
    u64 r; asm("add.rn.f32x2 %0,%1,%2;" : "=l"(r) : "l"(a), "l"(b)); return r;
}
__device__ __forceinline__ u64 fma2(u64 a, u64 b, u64 c) {
    u64 r; asm("fma.rn.f32x2 %0,%1,%2,%3;" : "=l"(r) : "l"(a), "l"(b), "l"(c)); return r;
}

// ---------------------------------------------------------------------------
// Fused kernel. Block (s=blockIdx.x in [0,39), b=blockIdx.y in [0,64)):
// processes rows t = s + 39k of batch b (only t < ml — invalid rows never
// visited). Warp w handles t = s + 39*w + 312*j. Lane owns 8 contiguous
// text positions n = 8*lane .. 8*lane+7. Gaussian via packed even/odd
// multiplicative recurrence. Last block (atomic ticket) finalizes.
// ---------------------------------------------------------------------------
__global__ __launch_bounds__(NTHR) void fused_kernel(
    const float* __restrict__ pred,
    const int*   __restrict__ tlen,
    const int*   __restrict__ mlen,
    float*       __restrict__ out)
{
    const int lane = threadIdx.x & 31;
    const int wid  = threadIdx.x >> 5;
    const int s    = blockIdx.x;          // t-phase
    const int b    = blockIdx.y;          // batch

    const int tl = __ldg(&tlen[b]);
    const int ml = __ldg(&mlen[b]);

    // ---- per-block / per-lane loop-invariant constants ----
    const float inv_tl = 1.0f / (float)tl;
    const float inv_ml = 1.0f / (float)ml;
    const int   n0     = lane * 8;
    const float alpha0 = (float)n0 * inv_tl;
    const float ca     = 2.0f * A_COEF * inv_tl * inv_ml;           // m0 = exp(ca*t + cb)
    const float cb     = -A_COEF * inv_tl * inv_tl * (float)(2 * n0 + 1);
    const float q2     = __expf(-2.0f * A_COEF * inv_tl * inv_tl);
    const float q2sq   = q2 * q2;
    const u64   Q4     = pk2(q2sq * q2sq, q2sq * q2sq);

    // per-lane element masks / load predicates (invariant)
    int count = tl - n0; if (count < 0) count = 0; if (count > 8) count = 8;
    const bool pred_lo = (count > 0);
    const bool pred_hi = (count > 4);
    const u64 mk0 = pk2(count > 0 ? 1.0f : 0.0f, count > 1 ? 1.0f : 0.0f);
    const u64 mk1 = pk2(count > 2 ? 1.0f : 0.0f, count > 3 ? 1.0f : 0.0f);
    const u64 mk2 = pk2(count > 4 ? 1.0f : 0.0f, count > 5 ? 1.0f : 0.0f);
    const u64 mk3 = pk2(count > 6 ? 1.0f : 0.0f, count > 7 ? 1.0f : 0.0f);

    // ---- row loop: t = s + 39*wid + 312*j, while t < ml ----
    int   t  = s + SSTRIDE * wid;
    float tf = (float)t;
    const float* rowp = pred + (size_t)b * (MEL_MAX * TXT_MAX)
                             + (size_t)t * TXT_MAX + n0;

    u64 tsp2  = 0;          // packed {0,0}
    u64 tsepA = 0, tsepB = 0;

    // zero-init so never-loaded halves contribute exactly 0
    ulonglong2 pA; pA.x = 0; pA.y = 0;
    ulonglong2 pB; pB.x = 0; pB.y = 0;

    for (; t < ml; t += SSTRIDE * 8, tf += (float)(SSTRIDE * 8),
                   rowp += (size_t)SSTRIDE * 8 * TXT_MAX) {
        // Gaussian seed for this row
        const float beta = tf * inv_ml;
        const float d0   = alpha0 - beta;
        const float E0   = __expf(-A_COEF * d0 * d0);
        const float m0   = __expf(fmaf(ca, tf, cb));

        // packed chains: E2 = {E(n0), E(n0+1)}, step ratio M2, ratio-of-ratio Q4
        const float m0sq = m0 * m0;
        const float m2lo = m0sq * q2;
        u64 E2 = pk2(E0, E0 * m0);
        u64 M2 = pk2(m2lo, m2lo * q2sq);

        // predicated vector loads (16B each); unloaded halves stay zero
        if (pred_lo) pA = *(const ulonglong2*)rowp;
        if (pred_hi) pB = *(const ulonglong2*)(rowp + 4);

        u64 mp;
        mp    = mul2(pA.x, mk0);
        tsp2  = add2(tsp2, mp);
        tsepA = fma2(E2, mp, tsepA);
        E2 = mul2(E2, M2); M2 = mul2(M2, Q4);

        mp    = mul2(pA.y, mk1);
        tsp2  = add2(tsp2, mp);
        tsepB = fma2(E2, mp, tsepB);
        E2 = mul2(E2, M2); M2 = mul2(M2, Q4);

        mp    = mul2(pB.x, mk2);
        tsp2  = add2(tsp2, mp);
        tsepA = fma2(E2, mp, tsepA);
        E2 = mul2(E2, M2);

        mp    = mul2(pB.y, mk3);
        tsp2  = add2(tsp2, mp);
        tsepB = fma2(E2, mp, tsepB);
    }

    // ---- reduce: loss = sum((1-E)p) = sum p - sum E p ----
    float a0, a1, b0, b1, c0, c1;
    unpk2(tsp2, a0, a1);
    unpk2(tsepA, b0, b1);
    unpk2(tsepB, c0, c1);
    float tot = (a0 + a1) - (b0 + b1 + c0 + c1);

    #pragma unroll
    for (int o = 16; o > 0; o >>= 1)
        tot += __shfl_xor_sync(0xFFFFFFFFu, tot, o);

    __shared__ double wsum[8];
    if (lane == 0) wsum[wid] = (double)tot;
    __syncthreads();

    __shared__ bool amLast;
    const int bid = blockIdx.y * SSTRIDE + blockIdx.x;
    if (threadIdx.x == 0) {
        double sacc = 0.0;
        #pragma unroll
        for (int k = 0; k < 8; k++) sacc += wsum[k];
        g_block[bid] = sacc;
        __threadfence();
        amLast = (atomicAdd(&g_count, 1u) == NBLK - 1);
    }
    __syncthreads();

    if (amLast) {
        __threadfence();
        double sv = 0.0;
        for (int k = threadIdx.x; k < NBLK; k += NTHR)
            sv += __ldcg(&g_block[k]);
        double sa = 0.0;
        if (threadIdx.x < BATCH)
            sa = (double)__ldg(&tlen[threadIdx.x]) * (double)__ldg(&mlen[threadIdx.x]);

        #pragma unroll
        for (int o = 16; o > 0; o >>= 1) {
            sv += __shfl_xor_sync(0xFFFFFFFFu, sv, o);
            sa += __shfl_xor_sync(0xFFFFFFFFu, sa, o);
        }

        __shared__ double fv[8], fa[8];
        if (lane == 0) { fv[wid] = sv; fa[wid] = sa; }
        __syncthreads();

        if (threadIdx.x == 0) {
            double tv = 0.0, ta = 0.0;
            #pragma unroll
            for (int k = 0; k < 8; k++) { tv += fv[k]; ta += fa[k]; }
            out[0] = (float)(tv / ta);   // attention_weight = 1.0
            g_count = 0;                 // reset for next graph replay
        }
    }
}

// ---------------------------------------------------------------------------
// Inputs (metadata order): targets (unused), predictions, text_lengths,
// mel_lengths. Output: single float.
// ---------------------------------------------------------------------------
extern "C" void kernel_launch(void* const* d_in, const int* in_sizes, int n_in,
                              void* d_out, int out_size)
{
    (void)in_sizes; (void)n_in; (void)out_size;
    const float* pred = (const float*)d_in[1];
    const int*   tlen = (const int*)d_in[2];
    const int*   mlen = (const int*)d_in[3];
    float*       out  = (float*)d_out;

    dim3 grid(SSTRIDE, BATCH);
    fused_kernel<<<grid, NTHR>>>(pred, tlen, mlen, out);
}

// round 7
// speedup vs baseline: 1.4324x; 1.2120x over previous
#include <cuda_runtime.h>
#include <cstdint>

// Problem constants: B=64, MEL_MAX=2000, TEXT_MAX=256, g=0.2
#define BATCH   64
#define MEL_MAX 2000
#define TXT_MAX 256
#define A_COEF  12.5f            // 1/(2 g^2)

#define NBPB    7                // blocks per batch
#define WPB     (NBPB * 8)       // 56 warps per batch (t-stride)
#define NBLK    (NBPB * BATCH)   // 448 blocks
#define NTHR    256

typedef unsigned long long u64;

// Scratch (__device__ globals — no allocation allowed)
__device__ double       g_block[NBLK];
__device__ unsigned int g_count = 0;

// ---- packed f32x2 helpers (Blackwell) ----
__device__ __forceinline__ u64 pk2(float lo, float hi) {
    u64 r; asm("mov.b64 %0,{%1,%2};" : "=l"(r) : "f"(lo), "f"(hi)); return r;
}
__device__ __forceinline__ void unpk2(u64 a, float& lo, float& hi) {
    asm("mov.b64 {%0,%1},%2;" : "=f"(lo), "=f"(hi) : "l"(a));
}
__device__ __forceinline__ u64 mul2(u64 a, u64 b) {
    u64 r; asm("mul.rn.f32x2 %0,%1,%2;" : "=l"(r) : "l"(a), "l"(b)); return r;
}
__device__ __forceinline__ u64 add2(u64 a, u64 b) {
    u64 r; asm("add.rn.f32x2 %0,%1,%2;" : "=l"(r) : "l"(a), "l"(b)); return r;
}
__device__ __forceinline__ u64 fma2(u64 a, u64 b, u64 c) {
    u64 r; asm("fma.rn.f32x2 %0,%1,%2,%3;" : "=l"(r) : "l"(a), "l"(b), "l"(c)); return r;
}

// ---------------------------------------------------------------------------
// Fused kernel. Block (x in [0,7), b=blockIdx.y): warp w_in_batch = x*8+wid
// handles rows t = w_in_batch + 56*j of batch b (t < ml only). Lane owns 8
// contiguous text positions n = 8*lane..8*lane+7. Gaussian via packed
// even/odd multiplicative recurrence; 2 rows per iteration for MLP/ILP.
// Last block (atomic ticket) reduces partials + normalizer, writes scalar.
// ---------------------------------------------------------------------------
__global__ __launch_bounds__(NTHR) void fused_kernel(
    const float* __restrict__ pred,
    const int*   __restrict__ tlen,
    const int*   __restrict__ mlen,
    float*       __restrict__ out)
{
    const int lane = threadIdx.x & 31;
    const int wid  = threadIdx.x >> 5;
    const int b    = blockIdx.y;
    const int wib  = blockIdx.x * 8 + wid;   // warp index within batch [0,56)

    const int tl = __ldg(&tlen[b]);
    const int ml = __ldg(&mlen[b]);

    // ---- loop-invariant per-block / per-lane constants ----
    const float inv_tl = 1.0f / (float)tl;
    const float inv_ml = 1.0f / (float)ml;
    const int   n0     = lane * 8;
    const float alpha0 = (float)n0 * inv_tl;
    const float ca     = 2.0f * A_COEF * inv_tl * inv_ml;   // m0 = exp(ca*t + cb)
    const float cb     = -A_COEF * inv_tl * inv_tl * (float)(2 * n0 + 1);
    const float q2     = __expf(-2.0f * A_COEF * inv_tl * inv_tl);
    const float q2sq   = q2 * q2;
    const float q8     = q2sq * q2sq;
    const u64   Q4     = pk2(q8, q8);

    int count = tl - n0; if (count < 0) count = 0; if (count > 8) count = 8;
    const bool pred_lo = (count > 0);
    const bool pred_hi = (count > 4);
    const u64 mk0 = pk2(count > 0 ? 1.0f : 0.0f, count > 1 ? 1.0f : 0.0f);
    const u64 mk1 = pk2(count > 2 ? 1.0f : 0.0f, count > 3 ? 1.0f : 0.0f);
    const u64 mk2 = pk2(count > 4 ? 1.0f : 0.0f, count > 5 ? 1.0f : 0.0f);
    const u64 mk3 = pk2(count > 6 ? 1.0f : 0.0f, count > 7 ? 1.0f : 0.0f);

    // accumulators (separate per unrolled row for ILP)
    u64 sp0 = 0, sA0 = 0, sB0 = 0;
    u64 sp1 = 0, sA1 = 0, sB1 = 0;

    int   t    = wib;
    float tf   = (float)t;
    const float* rowp = pred + (size_t)b * (MEL_MAX * TXT_MAX)
                             + (size_t)t * TXT_MAX + n0;
    const size_t rstep = (size_t)WPB * TXT_MAX;

    // ---- main loop: two rows (t, t+56) per iteration ----
    for (; t + WPB < ml; t += 2 * WPB, tf += (float)(2 * WPB), rowp += 2 * rstep) {
        // front-batched loads for both rows (MLP)
        ulonglong2 a0; a0.x = 0; a0.y = 0;
        ulonglong2 b0; b0.x = 0; b0.y = 0;
        ulonglong2 a1; a1.x = 0; a1.y = 0;
        ulonglong2 b1; b1.x = 0; b1.y = 0;
        const float* r1 = rowp + rstep;
        if (pred_lo) { a0 = *(const ulonglong2*)rowp;       a1 = *(const ulonglong2*)r1; }
        if (pred_hi) { b0 = *(const ulonglong2*)(rowp + 4); b1 = *(const ulonglong2*)(r1 + 4); }

        // seeds for both rows (MUFUs overlap)
        const float beta0 = tf * inv_ml;
        const float dd0   = alpha0 - beta0;
        const float E0a   = __expf(-A_COEF * dd0 * dd0);
        const float m0a   = __expf(fmaf(ca, tf, cb));
        const float tf1   = tf + (float)WPB;
        const float beta1 = tf1 * inv_ml;
        const float dd1   = alpha0 - beta1;
        const float E0b   = __expf(-A_COEF * dd1 * dd1);
        const float m0b   = __expf(fmaf(ca, tf1, cb));

        // row 0 packed chain
        {
            const float ms = m0a * m0a;
            const float m2 = ms * q2;
            u64 E2 = pk2(E0a, E0a * m0a);
            u64 M2 = pk2(m2, m2 * q2sq);
            u64 mp;
            mp = mul2(a0.x, mk0); sp0 = add2(sp0, mp); sA0 = fma2(E2, mp, sA0);
            E2 = mul2(E2, M2); M2 = mul2(M2, Q4);
            mp = mul2(a0.y, mk1); sp0 = add2(sp0, mp); sB0 = fma2(E2, mp, sB0);
            E2 = mul2(E2, M2); M2 = mul2(M2, Q4);
            mp = mul2(b0.x, mk2); sp0 = add2(sp0, mp); sA0 = fma2(E2, mp, sA0);
            E2 = mul2(E2, M2);
            mp = mul2(b0.y, mk3); sp0 = add2(sp0, mp); sB0 = fma2(E2, mp, sB0);
        }
        // row 1 packed chain (independent)
        {
            const float ms = m0b * m0b;
            const float m2 = ms * q2;
            u64 E2 = pk2(E0b, E0b * m0b);
            u64 M2 = pk2(m2, m2 * q2sq);
            u64 mp;
            mp = mul2(a1.x, mk0); sp1 = add2(sp1, mp); sA1 = fma2(E2, mp, sA1);
            E2 = mul2(E2, M2); M2 = mul2(M2, Q4);
            mp = mul2(a1.y, mk1); sp1 = add2(sp1, mp); sB1 = fma2(E2, mp, sB1);
            E2 = mul2(E2, M2); M2 = mul2(M2, Q4);
            mp = mul2(b1.x, mk2); sp1 = add2(sp1, mp); sA1 = fma2(E2, mp, sA1);
            E2 = mul2(E2, M2);
            mp = mul2(b1.y, mk3); sp1 = add2(sp1, mp); sB1 = fma2(E2, mp, sB1);
        }
    }

    // ---- tail: at most one remaining row ----
    if (t < ml) {
        ulonglong2 a0; a0.x = 0; a0.y = 0;
        ulonglong2 b0; b0.x = 0; b0.y = 0;
        if (pred_lo) a0 = *(const ulonglong2*)rowp;
        if (pred_hi) b0 = *(const ulonglong2*)(rowp + 4);

        const float beta0 = tf * inv_ml;
        const float dd0   = alpha0 - beta0;
        const float E0a   = __expf(-A_COEF * dd0 * dd0);
        const float m0a   = __expf(fmaf(ca, tf, cb));
        const float ms    = m0a * m0a;
        const float m2    = ms * q2;
        u64 E2 = pk2(E0a, E0a * m0a);
        u64 M2 = pk2(m2, m2 * q2sq);
        u64 mp;
        mp = mul2(a0.x, mk0); sp0 = add2(sp0, mp); sA0 = fma2(E2, mp, sA0);
        E2 = mul2(E2, M2); M2 = mul2(M2, Q4);
        mp = mul2(a0.y, mk1); sp0 = add2(sp0, mp); sB0 = fma2(E2, mp, sB0);
        E2 = mul2(E2, M2); M2 = mul2(M2, Q4);
        mp = mul2(b0.x, mk2); sp0 = add2(sp0, mp); sA0 = fma2(E2, mp, sA0);
        E2 = mul2(E2, M2);
        mp = mul2(b0.y, mk3); sp0 = add2(sp0, mp); sB0 = fma2(E2, mp, sB0);
    }

    // ---- combine: loss = sum p - sum E p ----
    u64 spT = add2(sp0, sp1);
    u64 seT = add2(add2(sA0, sB0), add2(sA1, sB1));
    float x0, x1, y0, y1;
    unpk2(spT, x0, x1);
    unpk2(seT, y0, y1);
    float tot = (x0 + x1) - (y0 + y1);

    #pragma unroll
    for (int o = 16; o > 0; o >>= 1)
        tot += __shfl_xor_sync(0xFFFFFFFFu, tot, o);

    __shared__ double wsum[8];
    if (lane == 0) wsum[wid] = (double)tot;
    __syncthreads();

    __shared__ bool amLast;
    const int bid = blockIdx.y * NBPB + blockIdx.x;
    if (threadIdx.x == 0) {
        double sacc = 0.0;
        #pragma unroll
        for (int k = 0; k < 8; k++) sacc += wsum[k];
        g_block[bid] = sacc;
        __threadfence();
        amLast = (atomicAdd(&g_count, 1u) == NBLK - 1);
    }
    __syncthreads();

    // ---- last block: final reduction + normalizer ----
    if (amLast) {
        __threadfence();
        double sv = 0.0;
        for (int k = threadIdx.x; k < NBLK; k += NTHR)
            sv += __ldcg(&g_block[k]);
        double sa = 0.0;
        if (threadIdx.x < BATCH)
            sa = (double)__ldg(&tlen[threadIdx.x]) * (double)__ldg(&mlen[threadIdx.x]);

        #pragma unroll
        for (int o = 16; o > 0; o >>= 1) {
            sv += __shfl_xor_sync(0xFFFFFFFFu, sv, o);
            sa += __shfl_xor_sync(0xFFFFFFFFu, sa, o);
        }

        __shared__ double fv[8], fa[8];
        if (lane == 0) { fv[wid] = sv; fa[wid] = sa; }
        __syncthreads();

        if (threadIdx.x == 0) {
            double tv = 0.0, ta = 0.0;
            #pragma unroll
            for (int k = 0; k < 8; k++) { tv += fv[k]; ta += fa[k]; }
            out[0] = (float)(tv / ta);   // attention_weight = 1.0
            g_count = 0;                 // reset for next graph replay
        }
    }
}

// ---------------------------------------------------------------------------
// Inputs (metadata order): targets (unused), predictions, text_lengths,
// mel_lengths. Output: single float.
// ---------------------------------------------------------------------------
extern "C" void kernel_launch(void* const* d_in, const int* in_sizes, int n_in,
                              void* d_out, int out_size)
{
    (void)in_sizes; (void)n_in; (void)out_size;
    const float* pred = (const float*)d_in[1];
    const int*   tlen = (const int*)d_in[2];
    const int*   mlen = (const int*)d_in[3];
    float*       out  = (float*)d_out;

    dim3 grid(NBPB, BATCH);
    fused_kernel<<<grid, NTHR>>>(pred, tlen, mlen, out);
}

// round 9
// speedup vs baseline: 1.6250x; 1.1345x over previous
#include <cuda_runtime.h>
#include <cstdint>

// Problem constants: B=64, MEL_MAX=2000, TEXT_MAX=256, g=0.2
#define BATCH   64
#define MEL_MAX 2000
#define TXT_MAX 256
#define A_COEF  12.5f            // 1/(2 g^2)

#define SLABS   16               // t-slabs per batch
#define SLAB    125              // rows per slab (16*125 = 2000)
#define NBLK    (SLABS * BATCH)  // 1024 blocks
#define NTHR    256              // 8 warps; warp strides t by 8 within slab

typedef unsigned long long u64;

// Scratch (__device__ globals — no allocation allowed)
__device__ double       g_block[NBLK];
__device__ unsigned int g_count = 0;

// ---- packed f32x2 helpers (Blackwell) ----
__device__ __forceinline__ u64 pk2(float lo, float hi) {
    u64 r; asm("mov.b64 %0,{%1,%2};" : "=l"(r) : "f"(lo), "f"(hi)); return r;
}
__device__ __forceinline__ void unpk2(u64 a, float& lo, float& hi) {
    asm("mov.b64 {%0,%1},%2;" : "=f"(lo), "=f"(hi) : "l"(a));
}
__device__ __forceinline__ u64 mul2(u64 a, u64 b) {
    u64 r; asm("mul.rn.f32x2 %0,%1,%2;" : "=l"(r) : "l"(a), "l"(b)); return r;
}
__device__ __forceinline__ u64 add2(u64 a, u64 b) {
    u64 r; asm("add.rn.f32x2 %0,%1,%2;" : "=l"(r) : "l"(a), "l"(b)); return r;
}
__device__ __forceinline__ u64 fma2(u64 a, u64 b, u64 c) {
    u64 r; asm("fma.rn.f32x2 %0,%1,%2,%3;" : "=l"(r) : "l"(a), "l"(b), "l"(c)); return r;
}

// ---------------------------------------------------------------------------
// Fused kernel, slab-balanced. Block (x, b) owns t in [125x, min(125(x+1),ml))
// of batch b; warp w handles t = 125x + w + 8k. Lane owns 8 contiguous text
// positions. Gaussian fully recurrent in BOTH axes (no MUFU in the loop).
// Last block (atomic ticket) reduces partials + normalizer.
// ---------------------------------------------------------------------------
__global__ __launch_bounds__(NTHR, 4) void fused_kernel(
    const float* __restrict__ pred,
    const int*   __restrict__ tlen,
    const int*   __restrict__ mlen,
    float*       __restrict__ out)
{
    const int lane = threadIdx.x & 31;
    const int wid  = threadIdx.x >> 5;
    const int b    = blockIdx.y;
    const int x    = blockIdx.x;

    const int ml    = __ldg(&mlen[b]);
    const int tbase = x * SLAB;

    u64 sP = 0, sE = 0;   // packed accumulators: sum p, sum E*p

    if (tbase < ml) {
        const int tl   = __ldg(&tlen[b]);
        const int tend = (tbase + SLAB < ml) ? tbase + SLAB : ml;

        // ---- loop-invariant constants ----
        const float inv_tl = 1.0f / (float)tl;
        const float inv_ml = 1.0f / (float)ml;
        const int   n0     = lane * 8;
        const float alpha0 = (float)n0 * inv_tl;
        const float ca     = 2.0f * A_COEF * inv_tl * inv_ml;
        const float cb     = -A_COEF * inv_tl * inv_tl * (float)(2 * n0 + 1);
        const float q2     = __expf(-2.0f * A_COEF * inv_tl * inv_tl);
        const float q2sq   = q2 * q2;
        const float q8     = q2sq * q2sq;
        const u64   Q4     = pk2(q8, q8);

        int count = tl - n0; if (count < 0) count = 0; if (count > 8) count = 8;
        const bool pred_lo = (count > 0);
        const bool pred_hi = (count > 4);
        const u64 mk0 = pk2(count > 0 ? 1.0f : 0.0f, count > 1 ? 1.0f : 0.0f);
        const u64 mk1 = pk2(count > 2 ? 1.0f : 0.0f, count > 3 ? 1.0f : 0.0f);
        const u64 mk2 = pk2(count > 4 ? 1.0f : 0.0f, count > 5 ? 1.0f : 0.0f);
        const u64 mk3 = pk2(count > 6 ? 1.0f : 0.0f, count > 7 ? 1.0f : 0.0f);

        // ---- t-direction seed recurrence (stride 8) ----
        // E0(t)=exp(-A u^2), u=alpha0-t/ml ; r=E0(t+8)/E0(t); r(t+8)=r(t)*S
        // m0(t)=exp(ca t + cb); m0(t+8)=m0(t)*RM
        const int   t0  = tbase + wid;
        const float di  = 8.0f * inv_ml;
        const float u0v = alpha0 - (float)t0 * inv_ml;
        float S  = __expf(-2.0f * A_COEF * di * di);
        float E0 = __expf(-A_COEF * u0v * u0v);
        float rr = __expf(2.0f * A_COEF * di * u0v - A_COEF * di * di);
        float m0 = __expf(fmaf(ca, (float)t0, cb));
        float RM = __expf(8.0f * ca);
        if (!pred_lo) { E0 = 0.0f; rr = 0.0f; m0 = 0.0f; RM = 0.0f; }

        // column chain for one row (validated recurrence, packed even/odd)
        auto chain = [&](float E0v, float m0v, ulonglong2 lo, ulonglong2 hi) {
            const float ms = m0v * m0v;
            const float m2 = ms * q2;
            u64 E2 = pk2(E0v, E0v * m0v);
            u64 M2 = pk2(m2, m2 * q2sq);
            u64 mp;
            mp = mul2(lo.x, mk0); sP = add2(sP, mp); sE = fma2(E2, mp, sE);
            E2 = mul2(E2, M2); M2 = mul2(M2, Q4);
            mp = mul2(lo.y, mk1); sP = add2(sP, mp); sE = fma2(E2, mp, sE);
            E2 = mul2(E2, M2); M2 = mul2(M2, Q4);
            mp = mul2(hi.x, mk2); sP = add2(sP, mp); sE = fma2(E2, mp, sE);
            E2 = mul2(E2, M2);
            mp = mul2(hi.y, mk3); sP = add2(sP, mp); sE = fma2(E2, mp, sE);
        };

        const float* rowp = pred + (size_t)b * (MEL_MAX * TXT_MAX)
                                 + (size_t)t0 * TXT_MAX + n0;
        int t = t0;

        // ---- main loop: rows t and t+8 per iteration ----
        for (; t + 8 < tend; t += 16, rowp += (size_t)16 * TXT_MAX) {
            ulonglong2 a0; a0.x = 0; a0.y = 0;
            ulonglong2 b0; b0.x = 0; b0.y = 0;
            ulonglong2 a1; a1.x = 0; a1.y = 0;
            ulonglong2 b1; b1.x = 0; b1.y = 0;
            const float* r1 = rowp + (size_t)8 * TXT_MAX;
            if (pred_lo) { a0 = *(const ulonglong2*)rowp;       a1 = *(const ulonglong2*)r1; }
            if (pred_hi) { b0 = *(const ulonglong2*)(rowp + 4); b1 = *(const ulonglong2*)(r1 + 4); }

            const float E0a = E0, m0a = m0;
            E0 *= rr; rr *= S; m0 *= RM;
            const float E0b = E0, m0b = m0;
            E0 *= rr; rr *= S; m0 *= RM;

            chain(E0a, m0a, a0, b0);
            chain(E0b, m0b, a1, b1);
        }

        // ---- tail: at most one row ----
        if (t < tend) {
            ulonglong2 a0; a0.x = 0; a0.y = 0;
            ulonglong2 b0; b0.x = 0; b0.y = 0;
            if (pred_lo) a0 = *(const ulonglong2*)rowp;
            if (pred_hi) b0 = *(const ulonglong2*)(rowp + 4);
            chain(E0, m0, a0, b0);
        }
    }

    // ---- combine: loss = sum p - sum E p ----
    float x0, x1, y0, y1;
    unpk2(sP, x0, x1);
    unpk2(sE, y0, y1);
    float tot = (x0 + x1) - (y0 + y1);

    #pragma unroll
    for (int o = 16; o > 0; o >>= 1)
        tot += __shfl_xor_sync(0xFFFFFFFFu, tot, o);

    __shared__ double wsum[8];
    if (lane == 0) wsum[wid] = (double)tot;
    __syncthreads();

    __shared__ bool amLast;
    const int bid = blockIdx.y * SLABS + blockIdx.x;
    if (threadIdx.x == 0) {
        double sacc = 0.0;
        #pragma unroll
        for (int k = 0; k < 8; k++) sacc += wsum[k];
        g_block[bid] = sacc;
        __threadfence();
        amLast = (atomicAdd(&g_count, 1u) == NBLK - 1);
    }
    __syncthreads();

    // ---- last block: final reduction + normalizer ----
    if (amLast) {
        __threadfence();
        double sv = 0.0;
        for (int k = threadIdx.x; k < NBLK; k += NTHR)
            sv += __ldcg(&g_block[k]);
        double sa = 0.0;
        if (threadIdx.x < BATCH)
            sa = (double)__ldg(&tlen[threadIdx.x]) * (double)__ldg(&mlen[threadIdx.x]);

        #pragma unroll
        for (int o = 16; o > 0; o >>= 1) {
            sv += __shfl_xor_sync(0xFFFFFFFFu, sv, o);
            sa += __shfl_xor_sync(0xFFFFFFFFu, sa, o);
        }

        __shared__ double fv[8], fa[8];
        if (lane == 0) { fv[wid] = sv; fa[wid] = sa; }
        __syncthreads();

        if (threadIdx.x == 0) {
            double tv = 0.0, ta = 0.0;
            #pragma unroll
            for (int k = 0; k < 8; k++) { tv += fv[k]; ta += fa[k]; }
            out[0] = (float)(tv / ta);   // attention_weight = 1.0
            g_count = 0;                 // reset for next graph replay
        }
    }
}

// ---------------------------------------------------------------------------
// Inputs (metadata order): targets (unused), predictions, text_lengths,
// mel_lengths. Output: single float.
// ---------------------------------------------------------------------------
extern "C" void kernel_launch(void* const* d_in, const int* in_sizes, int n_in,
                              void* d_out, int out_size)
{
    (void)in_sizes; (void)n_in; (void)out_size;
    const float* pred = (const float*)d_in[1];
    const int*   tlen = (const int*)d_in[2];
    const int*   mlen = (const int*)d_in[3];
    float*       out  = (float*)d_out;

    dim3 grid(SLABS, BATCH);
    fused_kernel<<<grid, NTHR>>>(pred, tlen, mlen, out);
}